// round 12
// baseline (speedup 1.0000x reference)
#include <cuda_runtime.h>
#include <math.h>

#define BB 2
#define NSEQ 2048
#define DMODEL 512
#define VOCAB 32000
#define DEPTH 6
#define NH 8
#define DH 64
#define DFF 2048
#define MROWS (BB * NSEQ)          // 4096
#define RES_SCALE 1.8612097182041991f   // (2*6)^0.25
#define ATT_SCALE 8.0f
#define EPS_LN 1e-5f
#define EPS_L2 1e-12f

// -------- scratch (device globals; no runtime allocation allowed) --------
__device__ __align__(16) float g_h[MROWS * DMODEL];
__device__ __align__(16) float g_q[MROWS * DMODEL];
__device__ __align__(16) float g_k[MROWS * DMODEL];
__device__ __align__(16) float g_v[MROWS * DMODEL];
__device__ __align__(16) float g_o[MROWS * DMODEL];
__device__ __align__(16) float g_ff[MROWS * DFF];

// ------------------------- embedding -------------------------
__global__ void embed_kernel(const int* __restrict__ x,
                             const float* __restrict__ tok,
                             const float* __restrict__ pos) {
    int row = blockIdx.x;
    int n = row % NSEQ;
    int t = x[row];
    int c = threadIdx.x * 4;
    float4 a = *(const float4*)&tok[(size_t)t * DMODEL + c];
    float4 p = *(const float4*)&pos[(size_t)n * DMODEL + c];
    a.x += p.x; a.y += p.y; a.z += p.z; a.w += p.w;
    *(float4*)&g_h[(size_t)row * DMODEL + c] = a;
}

// ------------------------- TF32 helpers -------------------------
__device__ __forceinline__ unsigned f2tf(float x) {
    unsigned r;
    asm("cvt.rna.tf32.f32 %0, %1;" : "=r"(r) : "f"(x));
    return r;
}
#define MMA_TF32(ACC, A0, A1, A2, A3, B0, B1)                                \
    asm volatile(                                                            \
        "mma.sync.aligned.m16n8k8.row.col.f32.tf32.tf32.f32 "                \
        "{%0,%1,%2,%3}, {%4,%5,%6,%7}, {%8,%9}, {%0,%1,%2,%3};"              \
        : "+f"((ACC)[0]), "+f"((ACC)[1]), "+f"((ACC)[2]), "+f"((ACC)[3])     \
        : "r"(A0), "r"(A1), "r"(A2), "r"(A3), "r"(B0), "r"(B1))

__device__ __forceinline__ void cp16(float* s, const float* g) {
    unsigned sa = (unsigned)__cvta_generic_to_shared(s);
    asm volatile("cp.async.cg.shared.global [%0], [%1], 16;" :: "r"(sa), "l"(g));
}

// ------------------------- TF32 tensor-core GEMM -------------------------
// Double-buffered cp.async; tf32 conversion done IN-PLACE in SMEM once per
// k-tile (each thread converts the 32 floats it fetched), so the MMA loop
// reads ready tf32 bits with no ALU on the critical path.
#define APADF 36
#define BPADF 132
#define SMEM_GEMM_BYTES ((2 * 128 * APADF + 2 * 32 * BPADF) * 4)   // 70656

template <int EPI>
__device__ __forceinline__ void gemm_body(
    const float* __restrict__ A, const float* __restrict__ Bw,
    float* __restrict__ C, int Nd, int Kd, int rowBase, int colBase,
    char* smemRaw) {
    float (*As)[128][APADF] = (float(*)[128][APADF])smemRaw;
    float (*Bs)[32][BPADF]  = (float(*)[32][BPADF])(smemRaw + 2 * 128 * APADF * 4);

    int tid = threadIdx.x;
    int warp = tid >> 5, lane = tid & 31;
    int wm = warp >> 2, wn = warp & 3;
    int lr = lane >> 2, lc = lane & 3;

    float acc[4][4][4];
#pragma unroll
    for (int i = 0; i < 4; i++)
#pragma unroll
        for (int j = 0; j < 4; j++)
#pragma unroll
            for (int r = 0; r < 4; r++) acc[i][j][r] = 0.f;

#pragma unroll
    for (int i = 0; i < 4; i++) {
        int idx = tid + i * 256;
        int r = idx >> 3, c = (idx & 7) * 4;
        cp16(&As[0][r][c], &A[(size_t)(rowBase + r) * Kd + c]);
    }
#pragma unroll
    for (int i = 0; i < 4; i++) {
        int idx = tid + i * 256;
        int r = idx >> 5, c = (idx & 31) * 4;
        cp16(&Bs[0][r][c], &Bw[(size_t)r * Nd + colBase + c]);
    }
    asm volatile("cp.async.commit_group;");

    int KT = Kd >> 5;
    for (int kt = 0; kt < KT; kt++) {
        if (kt + 1 < KT) {
            int k0 = (kt + 1) << 5;
            int nb = (kt + 1) & 1;
#pragma unroll
            for (int i = 0; i < 4; i++) {
                int idx = tid + i * 256;
                int r = idx >> 3, c = (idx & 7) * 4;
                cp16(&As[nb][r][c], &A[(size_t)(rowBase + r) * Kd + k0 + c]);
            }
#pragma unroll
            for (int i = 0; i < 4; i++) {
                int idx = tid + i * 256;
                int r = idx >> 5, c = (idx & 31) * 4;
                cp16(&Bs[nb][r][c], &Bw[(size_t)(k0 + r) * Nd + colBase + c]);
            }
            asm volatile("cp.async.commit_group;");
            asm volatile("cp.async.wait_group 1;");
        } else {
            asm volatile("cp.async.wait_group 0;");
        }
        __syncthreads();

        int buf = kt & 1;
        // ---- in-place tf32 conversion (each thread: its own 32 floats) ----
#pragma unroll
        for (int i = 0; i < 4; i++) {
            int idx = tid + i * 256;
            int r = idx >> 3, c = (idx & 7) * 4;
            float4 t = *(float4*)&As[buf][r][c];
            uint4 u = {f2tf(t.x), f2tf(t.y), f2tf(t.z), f2tf(t.w)};
            *(uint4*)&As[buf][r][c] = u;
        }
#pragma unroll
        for (int i = 0; i < 4; i++) {
            int idx = tid + i * 256;
            int r = idx >> 5, c = (idx & 31) * 4;
            float4 t = *(float4*)&Bs[buf][r][c];
            uint4 u = {f2tf(t.x), f2tf(t.y), f2tf(t.z), f2tf(t.w)};
            *(uint4*)&Bs[buf][r][c] = u;
        }
        __syncthreads();

        unsigned (*Au)[APADF] = (unsigned(*)[APADF])As[buf];
        unsigned (*Bu)[BPADF] = (unsigned(*)[BPADF])Bs[buf];
#pragma unroll
        for (int ks = 0; ks < 32; ks += 8) {
            unsigned af[4][4];
            unsigned bf[4][2];
#pragma unroll
            for (int i = 0; i < 4; i++) {
                int m0 = wm * 64 + i * 16;
                af[i][0] = Au[m0 + lr][ks + lc];
                af[i][1] = Au[m0 + lr + 8][ks + lc];
                af[i][2] = Au[m0 + lr][ks + lc + 4];
                af[i][3] = Au[m0 + lr + 8][ks + lc + 4];
            }
#pragma unroll
            for (int j = 0; j < 4; j++) {
                int n0 = wn * 32 + j * 8;
                bf[j][0] = Bu[ks + lc][n0 + lr];
                bf[j][1] = Bu[ks + lc + 4][n0 + lr];
            }
#pragma unroll
            for (int i = 0; i < 4; i++)
#pragma unroll
                for (int j = 0; j < 4; j++)
                    MMA_TF32(acc[i][j], af[i][0], af[i][1], af[i][2], af[i][3],
                             bf[j][0], bf[j][1]);
        }
        __syncthreads();
    }

    const float gc = 0.70710678118654752f;
#pragma unroll
    for (int i = 0; i < 4; i++) {
#pragma unroll
        for (int j = 0; j < 4; j++) {
            float v0 = acc[i][j][0], v1 = acc[i][j][1];
            float v2 = acc[i][j][2], v3 = acc[i][j][3];
            if (EPI == 1) {
                v0 = 0.5f * v0 * (1.0f + erff(v0 * gc));
                v1 = 0.5f * v1 * (1.0f + erff(v1 * gc));
                v2 = 0.5f * v2 * (1.0f + erff(v2 * gc));
                v3 = 0.5f * v3 * (1.0f + erff(v3 * gc));
            }
            int row = rowBase + wm * 64 + i * 16 + lr;
            int col = colBase + wn * 32 + j * 8 + lc * 2;
            float2 p0 = {v0, v1};
            float2 p1 = {v2, v3};
            *(float2*)&C[(size_t)row * Nd + col] = p0;
            *(float2*)&C[(size_t)(row + 8) * Nd + col] = p1;
        }
    }
}

template <int EPI>
__global__ __launch_bounds__(256, 2) void gemm_tc(
    const float* __restrict__ A, const float* __restrict__ Bw,
    float* __restrict__ C, int Nd, int Kd) {
    extern __shared__ char sm[];
    gemm_body<EPI>(A, Bw, C, Nd, Kd, blockIdx.y * 128, blockIdx.x * 128, sm);
}

__global__ __launch_bounds__(256, 2) void qkv_tc(
    const float* __restrict__ A,
    const float* __restrict__ Wq, const float* __restrict__ Wk,
    const float* __restrict__ Wv,
    float* __restrict__ q, float* __restrict__ k, float* __restrict__ v) {
    extern __shared__ char sm[];
    const float* Bw = (blockIdx.z == 0) ? Wq : (blockIdx.z == 1) ? Wk : Wv;
    float* C = (blockIdx.z == 0) ? q : (blockIdx.z == 1) ? k : v;
    gemm_body<0>(A, Bw, C, DMODEL, DMODEL, blockIdx.y * 128, blockIdx.x * 128, sm);
}

// ------------------------- TF32 MMA flash attention -------------------------
#define FPAD 68
#define SMEM_FLASH_BYTES (4 * 64 * FPAD * 4)   // 69632

__global__ __launch_bounds__(128, 3) void flash_tc(
    const float* __restrict__ Q, const float* __restrict__ K,
    const float* __restrict__ V, float* __restrict__ O) {
    extern __shared__ float fs[];
    float (*Qs)[FPAD] = (float(*)[FPAD])fs;
    float (*Ks)[FPAD] = (float(*)[FPAD])(fs + 64 * FPAD);
    float (*Vs)[FPAD] = (float(*)[FPAD])(fs + 2 * 64 * FPAD);
    float (*Ps)[FPAD] = (float(*)[FPAD])(fs + 3 * 64 * FPAD);

    int qt = blockIdx.x, bh = blockIdx.y;
    int b = bh >> 3, h = bh & 7;
    int tid = threadIdx.x;
    int warp = tid >> 5, lane = tid & 31;
    int lr = lane >> 2, lc = lane & 3;
    int q0 = qt * 64;
    int lrow = tid >> 1, half = tid & 1;
    int m0 = warp * 16;

    {
        const float* qp = Q + (size_t)(b * NSEQ + q0 + lrow) * DMODEL + h * DH + half * 32;
        float buf[32];
        float nrm = 0.f;
#pragma unroll
        for (int i = 0; i < 8; i++) {
            float4 t = ((const float4*)qp)[i];
            buf[i * 4 + 0] = t.x; buf[i * 4 + 1] = t.y;
            buf[i * 4 + 2] = t.z; buf[i * 4 + 3] = t.w;
            nrm += t.x * t.x + t.y * t.y + t.z * t.z + t.w * t.w;
        }
        nrm += __shfl_xor_sync(0xffffffffu, nrm, 1);
        float inv = 1.0f / fmaxf(sqrtf(nrm), EPS_L2);
#pragma unroll
        for (int i = 0; i < 32; i++) Qs[lrow][half * 32 + i] = buf[i] * inv;
    }

    float oacc[8][4];
#pragma unroll
    for (int j = 0; j < 8; j++)
#pragma unroll
        for (int r = 0; r < 4; r++) oacc[j][r] = 0.f;
    float l0 = 0.f, l1 = 0.f;

    for (int kv0 = 0; kv0 <= q0; kv0 += 64) {
        __syncthreads();
        {
            const float* kp = K + (size_t)(b * NSEQ + kv0 + lrow) * DMODEL + h * DH + half * 32;
            const float* vp = V + (size_t)(b * NSEQ + kv0 + lrow) * DMODEL + h * DH + half * 32;
            float buf[32];
            float nrm = 0.f;
#pragma unroll
            for (int i = 0; i < 8; i++) {
                float4 t = ((const float4*)kp)[i];
                buf[i * 4 + 0] = t.x; buf[i * 4 + 1] = t.y;
                buf[i * 4 + 2] = t.z; buf[i * 4 + 3] = t.w;
                nrm += t.x * t.x + t.y * t.y + t.z * t.z + t.w * t.w;
            }
            nrm += __shfl_xor_sync(0xffffffffu, nrm, 1);
            float inv = 1.0f / fmaxf(sqrtf(nrm), EPS_L2);
#pragma unroll
            for (int i = 0; i < 32; i++) Ks[lrow][half * 32 + i] = buf[i] * inv;
#pragma unroll
            for (int i = 0; i < 8; i++) {
                float4 t = ((const float4*)vp)[i];
                *(float4*)&Vs[lrow][half * 32 + i * 4] = t;
            }
        }
        __syncthreads();

        float sacc[8][4];
#pragma unroll
        for (int j = 0; j < 8; j++)
#pragma unroll
            for (int r = 0; r < 4; r++) sacc[j][r] = 0.f;
#pragma unroll
        for (int ks = 0; ks < 64; ks += 8) {
            unsigned a0 = f2tf(Qs[m0 + lr][ks + lc]);
            unsigned a1 = f2tf(Qs[m0 + lr + 8][ks + lc]);
            unsigned a2 = f2tf(Qs[m0 + lr][ks + lc + 4]);
            unsigned a3 = f2tf(Qs[m0 + lr + 8][ks + lc + 4]);
#pragma unroll
            for (int j = 0; j < 8; j++) {
                unsigned b0 = f2tf(Ks[j * 8 + lr][ks + lc]);
                unsigned b1 = f2tf(Ks[j * 8 + lr][ks + lc + 4]);
                MMA_TF32(sacc[j], a0, a1, a2, a3, b0, b1);
            }
        }

        int r0 = q0 + m0 + lr, r1 = r0 + 8;
        bool diag = (kv0 == q0);
        float lp0 = 0.f, lp1 = 0.f;
#pragma unroll
        for (int j = 0; j < 8; j++) {
            int c = kv0 + j * 8 + 2 * lc;
            float p00 = __expf(ATT_SCALE * sacc[j][0] - ATT_SCALE);
            float p01 = __expf(ATT_SCALE * sacc[j][1] - ATT_SCALE);
            float p10 = __expf(ATT_SCALE * sacc[j][2] - ATT_SCALE);
            float p11 = __expf(ATT_SCALE * sacc[j][3] - ATT_SCALE);
            if (diag) {
                if (c     > r0) p00 = 0.f;
                if (c + 1 > r0) p01 = 0.f;
                if (c     > r1) p10 = 0.f;
                if (c + 1 > r1) p11 = 0.f;
            }
            lp0 += p00 + p01;
            lp1 += p10 + p11;
            Ps[m0 + lr][j * 8 + 2 * lc]     = p00;
            Ps[m0 + lr][j * 8 + 2 * lc + 1] = p01;
            Ps[m0 + lr + 8][j * 8 + 2 * lc]     = p10;
            Ps[m0 + lr + 8][j * 8 + 2 * lc + 1] = p11;
        }
        lp0 += __shfl_xor_sync(0xffffffffu, lp0, 1);
        lp0 += __shfl_xor_sync(0xffffffffu, lp0, 2);
        lp1 += __shfl_xor_sync(0xffffffffu, lp1, 1);
        lp1 += __shfl_xor_sync(0xffffffffu, lp1, 2);
        l0 += lp0;
        l1 += lp1;
        __syncwarp();

#pragma unroll
        for (int ks = 0; ks < 64; ks += 8) {
            unsigned a0 = f2tf(Ps[m0 + lr][ks + lc]);
            unsigned a1 = f2tf(Ps[m0 + lr + 8][ks + lc]);
            unsigned a2 = f2tf(Ps[m0 + lr][ks + lc + 4]);
            unsigned a3 = f2tf(Ps[m0 + lr + 8][ks + lc + 4]);
#pragma unroll
            for (int j = 0; j < 8; j++) {
                unsigned b0 = f2tf(Vs[ks + lc][j * 8 + lr]);
                unsigned b1 = f2tf(Vs[ks + lc + 4][j * 8 + lr]);
                MMA_TF32(oacc[j], a0, a1, a2, a3, b0, b1);
            }
        }
    }

    float i0 = 1.0f / l0, i1 = 1.0f / l1;
    float* op0 = O + (size_t)(b * NSEQ + q0 + m0 + lr) * DMODEL + h * DH;
    float* op1 = op0 + (size_t)8 * DMODEL;
#pragma unroll
    for (int j = 0; j < 8; j++) {
        float2 p0 = {oacc[j][0] * i0, oacc[j][1] * i0};
        float2 p1 = {oacc[j][2] * i1, oacc[j][3] * i1};
        *(float2*)&op0[j * 8 + 2 * lc] = p0;
        *(float2*)&op1[j * 8 + 2 * lc] = p1;
    }
}

// ------------------------- residual + LayerNorm -------------------------
__global__ __launch_bounds__(128) void resid_ln_kernel(
    const float* __restrict__ a, float* __restrict__ hb,
    const float* __restrict__ g, const float* __restrict__ bt) {
    __shared__ float red[4];
    int row = blockIdx.x;
    int tid = threadIdx.x;
    const float* ar = a + (size_t)row * DMODEL;
    float* hr = hb + (size_t)row * DMODEL;

    float4 av = *(const float4*)&ar[tid * 4];
    float4 hv = *(const float4*)&hr[tid * 4];
    float v0 = av.x + hv.x * RES_SCALE;
    float v1 = av.y + hv.y * RES_SCALE;
    float v2 = av.z + hv.z * RES_SCALE;
    float v3 = av.w + hv.w * RES_SCALE;

    float s = v0 + v1 + v2 + v3;
#pragma unroll
    for (int o = 16; o > 0; o >>= 1) s += __shfl_xor_sync(0xffffffffu, s, o);
    if ((tid & 31) == 0) red[tid >> 5] = s;
    __syncthreads();
    float mean = (red[0] + red[1] + red[2] + red[3]) * (1.0f / DMODEL);

    float d0 = v0 - mean, d1 = v1 - mean, d2 = v2 - mean, d3 = v3 - mean;
    float sq = d0 * d0 + d1 * d1 + d2 * d2 + d3 * d3;
#pragma unroll
    for (int o = 16; o > 0; o >>= 1) sq += __shfl_xor_sync(0xffffffffu, sq, o);
    __syncthreads();
    if ((tid & 31) == 0) red[tid >> 5] = sq;
    __syncthreads();
    float var = (red[0] + red[1] + red[2] + red[3]) * (1.0f / DMODEL);
    float inv = rsqrtf(var + EPS_LN);

    float4 gv = *(const float4*)&g[tid * 4];
    float4 bv = *(const float4*)&bt[tid * 4];
    float4 outv;
    outv.x = d0 * inv * gv.x + bv.x;
    outv.y = d1 * inv * gv.y + bv.y;
    outv.z = d2 * inv * gv.z + bv.z;
    outv.w = d3 * inv * gv.w + bv.w;
    *(float4*)&hr[tid * 4] = outv;
}

// ------------------------- driver -------------------------
extern "C" void kernel_launch(void* const* d_in, const int* in_sizes, int n_in,
                              void* d_out, int out_size) {
    const int*   x    = (const int*)d_in[0];
    const float* tok  = (const float*)d_in[1];
    const float* pos  = (const float*)d_in[2];
    const float* Wq   = (const float*)d_in[3];
    const float* Wk   = (const float*)d_in[4];
    const float* Wv   = (const float*)d_in[5];
    const float* Wo   = (const float*)d_in[6];
    const float* ln1g = (const float*)d_in[7];
    const float* ln1b = (const float*)d_in[8];
    const float* W1   = (const float*)d_in[9];
    const float* W2   = (const float*)d_in[10];
    const float* ln2g = (const float*)d_in[11];
    const float* ln2b = (const float*)d_in[12];
    const float* Wlog = (const float*)d_in[13];
    float* out = (float*)d_out;

    float *h, *q, *k, *v, *o, *ff;
    cudaGetSymbolAddress((void**)&h,  g_h);
    cudaGetSymbolAddress((void**)&q,  g_q);
    cudaGetSymbolAddress((void**)&k,  g_k);
    cudaGetSymbolAddress((void**)&v,  g_v);
    cudaGetSymbolAddress((void**)&o,  g_o);
    cudaGetSymbolAddress((void**)&ff, g_ff);

    cudaFuncSetAttribute(gemm_tc<0>, cudaFuncAttributeMaxDynamicSharedMemorySize, SMEM_GEMM_BYTES);
    cudaFuncSetAttribute(gemm_tc<1>, cudaFuncAttributeMaxDynamicSharedMemorySize, SMEM_GEMM_BYTES);
    cudaFuncSetAttribute(qkv_tc,     cudaFuncAttributeMaxDynamicSharedMemorySize, SMEM_GEMM_BYTES);
    cudaFuncSetAttribute(flash_tc,   cudaFuncAttributeMaxDynamicSharedMemorySize, SMEM_FLASH_BYTES);

    embed_kernel<<<MROWS, 128>>>(x, tok, pos);

    const size_t wAttn = (size_t)DMODEL * NH * DH;
    const size_t wFF   = (size_t)DMODEL * DFF;
    const size_t vecD  = DMODEL;

    dim3 gQKV(DMODEL / 128, MROWS / 128, 3);
    dim3 gProj(DMODEL / 128, MROWS / 128);
    dim3 gFF1(DFF / 128, MROWS / 128);
    dim3 gLog(VOCAB / 128, MROWS / 128);
    dim3 gFlash(NSEQ / 64, BB * NH);

    for (int i = 0; i < DEPTH; i++) {
        qkv_tc<<<gQKV, 256, SMEM_GEMM_BYTES>>>(h, Wq + i * wAttn, Wk + i * wAttn,
                                               Wv + i * wAttn, q, k, v);
        flash_tc<<<gFlash, 128, SMEM_FLASH_BYTES>>>(q, k, v, o);
        gemm_tc<0><<<gProj, 256, SMEM_GEMM_BYTES>>>(o, Wo + i * wAttn, q, DMODEL, DMODEL);
        resid_ln_kernel<<<MROWS, 128>>>(q, h, ln1g + i * vecD, ln1b + i * vecD);
        gemm_tc<1><<<gFF1, 256, SMEM_GEMM_BYTES>>>(h, W1 + i * wFF, ff, DFF, DMODEL);
        gemm_tc<0><<<gProj, 256, SMEM_GEMM_BYTES>>>(ff, W2 + i * wFF, q, DMODEL, DFF);
        resid_ln_kernel<<<MROWS, 128>>>(q, h, ln2g + i * vecD, ln2b + i * vecD);
    }

    gemm_tc<0><<<gLog, 256, SMEM_GEMM_BYTES>>>(h, Wlog, out, VOCAB, DMODEL);
}